// round 1
// baseline (speedup 1.0000x reference)
#include <cuda_runtime.h>

// ---------------- scratch (device globals; no allocation) ----------------
__device__ float g_pre[16*64*1024];     // conv1 out, then h (in-place)
__device__ float g_S[16*64*9];          // 9 shifted window sums per (b, in-ch)
__device__ float g_scale[64];
__device__ float g_bnbias[64];
__device__ float g_Q[16*4*1024*10];
__device__ float g_Kb[16*4*1024*10];
__device__ float g_Vb[16*4*1024*10];
__device__ float g_attn[16*4*1024*10];
__device__ float g_pooled[16*88];

__device__ __forceinline__ float wred(float v) {
  #pragma unroll
  for (int o = 16; o; o >>= 1) v += __shfl_down_sync(0xffffffffu, v, o);
  return v;
}

// ---------------- K1: conv1 3x3 (3->64), SAME ----------------
__global__ void conv1_kernel(const float* __restrict__ x,
                             const float* __restrict__ w,
                             const float* __restrict__ bias) {
  int p = blockIdx.x * 256 + threadIdx.x;   // pixel 0..1023
  int oc = blockIdx.y, b = blockIdx.z;
  int y = p >> 5, xx = p & 31;
  float acc = __ldg(&bias[oc]);
  const float* wp = w + oc * 27;
  #pragma unroll
  for (int ic = 0; ic < 3; ic++) {
    const float* xp = x + (b * 3 + ic) * 1024;
    #pragma unroll
    for (int ky = 0; ky < 3; ky++) {
      int iy = y + ky - 1;
      if (iy < 0 || iy > 31) continue;
      #pragma unroll
      for (int kx = 0; kx < 3; kx++) {
        int ix = xx + kx - 1;
        if (ix < 0 || ix > 31) continue;
        acc = fmaf(__ldg(&xp[iy * 32 + ix]), __ldg(&wp[ic * 9 + ky * 3 + kx]), acc);
      }
    }
  }
  g_pre[(b * 64 + oc) * 1024 + p] = acc;
}

// ---------------- K2: BN batch stats -> scale/bias ----------------
__global__ void bnstats_kernel(const float* __restrict__ gamma,
                               const float* __restrict__ beta) {
  int c = blockIdx.x, tid = threadIdx.x;
  float s = 0.f, sq = 0.f;
  for (int j = tid; j < 16 * 1024; j += 256) {
    int b = j >> 10, p = j & 1023;
    float v = g_pre[(b * 64 + c) * 1024 + p];
    s += v; sq = fmaf(v, v, sq);
  }
  s = wred(s); sq = wred(sq);
  __shared__ float ss[8], s2[8];
  int warp = tid >> 5, lane = tid & 31;
  if (lane == 0) { ss[warp] = s; s2[warp] = sq; }
  __syncthreads();
  if (tid == 0) {
    float S = 0.f, Q = 0.f;
    #pragma unroll
    for (int i = 0; i < 8; i++) { S += ss[i]; Q += s2[i]; }
    float mean = S * (1.f / 16384.f);
    float var  = Q * (1.f / 16384.f) - mean * mean;
    float sc = __ldg(&gamma[c]) * rsqrtf(var + 1e-5f);
    g_scale[c]  = sc;
    g_bnbias[c] = __ldg(&beta[c]) - mean * sc;
  }
}

// ---------------- K3: BN apply + relu (in place) + 9 window sums ----------------
__global__ void bnrelu_kernel() {
  int c = blockIdx.x, b = blockIdx.y;
  int p = threadIdx.x;                  // 1024 threads
  int y = p >> 5, xx = p & 31;
  int idx = (b * 64 + c) * 1024 + p;
  float v = fmaxf(fmaf(g_pre[idx], g_scale[c], g_bnbias[c]), 0.f);
  g_pre[idx] = v;

  float t = v;
  float r0  = (y == 0)  ? v : 0.f;
  float r31 = (y == 31) ? v : 0.f;
  float c0  = (xx == 0)  ? v : 0.f;
  float c31 = (xx == 31) ? v : 0.f;

  __shared__ float red[32][5];
  __shared__ float corn[4];
  if (p == 0)    corn[0] = v;   // h[0,0]
  if (p == 31)   corn[1] = v;   // h[0,31]
  if (p == 992)  corn[2] = v;   // h[31,0]
  if (p == 1023) corn[3] = v;   // h[31,31]

  t = wred(t); r0 = wred(r0); r31 = wred(r31); c0 = wred(c0); c31 = wred(c31);
  int warp = p >> 5, lane = p & 31;
  if (lane == 0) { red[warp][0]=t; red[warp][1]=r0; red[warp][2]=r31; red[warp][3]=c0; red[warp][4]=c31; }
  __syncthreads();
  if (p < 32) {
    float a0 = red[p][0], a1 = red[p][1], a2 = red[p][2], a3 = red[p][3], a4 = red[p][4];
    a0 = wred(a0); a1 = wred(a1); a2 = wred(a2); a3 = wred(a3); a4 = wred(a4);
    if (p == 0) {
      float T = a0, R0 = a1, R31 = a2, C0 = a3, C31 = a4;
      float* Sp = g_S + (b * 64 + c) * 9;
      // Sp[ky*3+kx] = S(dy=ky-1, dx=kx-1)
      Sp[0] = T - R31 - C31 + corn[3];
      Sp[1] = T - R31;
      Sp[2] = T - R31 - C0 + corn[2];
      Sp[3] = T - C31;
      Sp[4] = T;
      Sp[5] = T - C0;
      Sp[6] = T - R0 - C31 + corn[1];
      Sp[7] = T - R0;
      Sp[8] = T - R0 - C0 + corn[0];
    }
  }
}

// ---------------- K4: pooled conv_out via window sums ----------------
__global__ void poolconv_kernel(const float* __restrict__ w,
                                const float* __restrict__ cb) {
  int b = blockIdx.x, tid = threadIdx.x;   // 96 threads
  __shared__ float Ssm[576];
  for (int i = tid; i < 576; i += 96) Ssm[i] = g_S[b * 576 + i];
  __syncthreads();
  if (tid < 88) {
    float acc = 0.f;
    const float* wp = w + tid * 576;
    #pragma unroll 4
    for (int i = 0; i < 576; i++) acc = fmaf(__ldg(&wp[i]), Ssm[i], acc);
    g_pooled[b * 88 + tid] = __ldg(&cb[tid]) + acc * (1.f / 1024.f);
  }
}

// ---------------- K5: qkv 1x1 conv -> Q (scaled), K, V [bh][n][10] ----------------
__global__ void qkv_kernel(const float* __restrict__ w,
                           const float* __restrict__ bias) {
  int tid = threadIdx.x;        // 256
  int b = blockIdx.z;
  int o0 = blockIdx.y * 8;      // 15 groups of 8 output channels
  __shared__ float ws[512];
  __shared__ float bs[8];
  for (int i = tid; i < 512; i += 256) ws[i] = w[o0 * 64 + i];  // [u][i]
  if (tid < 8) bs[tid] = bias[o0 + tid];
  __syncthreads();
  int n0 = tid * 4;
  float4 acc[8];
  #pragma unroll
  for (int u = 0; u < 8; u++) { float bv = bs[u]; acc[u] = make_float4(bv, bv, bv, bv); }
  const float* hp = g_pre + b * 64 * 1024 + n0;
  #pragma unroll 4
  for (int i = 0; i < 64; i++) {
    float4 hv = *(const float4*)(hp + i * 1024);
    #pragma unroll
    for (int u = 0; u < 8; u++) {
      float wv = ws[u * 64 + i];
      acc[u].x = fmaf(wv, hv.x, acc[u].x);
      acc[u].y = fmaf(wv, hv.y, acc[u].y);
      acc[u].z = fmaf(wv, hv.z, acc[u].z);
      acc[u].w = fmaf(wv, hv.w, acc[u].w);
    }
  }
  #pragma unroll
  for (int u = 0; u < 8; u++) {
    int o = o0 + u;
    int which = o / 40;
    int r = o - which * 40;
    int head = r / 10, d = r - head * 10;
    float* dst = (which == 0) ? g_Q : ((which == 1) ? g_Kb : g_Vb);
    float mul = (which == 0) ? 0.31622776601683794f : 1.f;   // dkh^-0.5
    float* pb = dst + ((b * 4 + head) * 1024) * 10 + d;
    pb[(n0 + 0) * 10] = acc[u].x * mul;
    pb[(n0 + 1) * 10] = acc[u].y * mul;
    pb[(n0 + 2) * 10] = acc[u].z * mul;
    pb[(n0 + 3) * 10] = acc[u].w * mul;
  }
}

// ---------------- K6: attention with rank-1 relative biases ----------------
#define ATTN_SMEM ((12288 + 12288 + 640) * 4)

__global__ void __launch_bounds__(128) attn_kernel(const float* __restrict__ krh,
                                                   const float* __restrict__ krw) {
  extern __shared__ float sm[];
  float* Ks = sm;             // [m][12] padded
  float* Vs = sm + 12288;     // [m][12] padded
  float* Hs = sm + 24576;     // key_rel_h 63*10
  int b = blockIdx.z, h = blockIdx.y;
  int bh = b * 4 + h;
  int tid = threadIdx.x;
  int warp = tid >> 5, lane = tid & 31;
  const float* Kp = g_Kb + bh * 10240;
  const float* Vp = g_Vb + bh * 10240;
  for (int i = tid; i < 12288; i += 128) {
    int m = i / 12, d = i - m * 12;
    float kv = 0.f, vv = 0.f;
    if (d < 10) { kv = Kp[m * 10 + d]; vv = Vp[m * 10 + d]; }
    Ks[i] = kv; Vs[i] = vv;
  }
  for (int i = tid; i < 630; i += 128) Hs[i] = krh[i];

  int yq = blockIdx.x * 4 + warp;   // warp = one query row
  int xq = lane;
  int n = yq * 32 + xq;
  const float* qp = g_Q + (bh * 1024 + n) * 10;
  float q0 = qp[0], q1 = qp[1], q2 = qp[2], q3 = qp[3], q4 = qp[4];
  float q5 = qp[5], q6 = qp[6], q7 = qp[7], q8 = qp[8], q9 = qp[9];

  // rw[xm] = q . key_rel_w[xm - xq + 31]
  float rw[32];
  #pragma unroll
  for (int xm = 0; xm < 32; xm++) {
    const float* kr = krw + (xm - xq + 31) * 10;
    float s = q0 * __ldg(&kr[0]);
    s = fmaf(q1, __ldg(&kr[1]), s); s = fmaf(q2, __ldg(&kr[2]), s);
    s = fmaf(q3, __ldg(&kr[3]), s); s = fmaf(q4, __ldg(&kr[4]), s);
    s = fmaf(q5, __ldg(&kr[5]), s); s = fmaf(q6, __ldg(&kr[6]), s);
    s = fmaf(q7, __ldg(&kr[7]), s); s = fmaf(q8, __ldg(&kr[8]), s);
    s = fmaf(q9, __ldg(&kr[9]), s);
    rw[xm] = s;
  }
  __syncthreads();

  float a0=0,a1=0,a2=0,a3=0,a4=0,a5=0,a6=0,a7=0,a8=0,a9=0;
  float l = 0.f;
  #pragma unroll 1
  for (int ym = 0; ym < 32; ym++) {
    const float* kh = Hs + (ym - yq + 31) * 10;   // broadcast (yq const per warp)
    float rh = q0 * kh[0];
    rh = fmaf(q1, kh[1], rh); rh = fmaf(q2, kh[2], rh);
    rh = fmaf(q3, kh[3], rh); rh = fmaf(q4, kh[4], rh);
    rh = fmaf(q5, kh[5], rh); rh = fmaf(q6, kh[6], rh);
    rh = fmaf(q7, kh[7], rh); rh = fmaf(q8, kh[8], rh);
    rh = fmaf(q9, kh[9], rh);
    const float4* kp = (const float4*)(Ks + ym * 384);
    const float4* vp = (const float4*)(Vs + ym * 384);
    #pragma unroll
    for (int xm = 0; xm < 32; xm++) {
      float4 k0 = kp[xm*3], k1 = kp[xm*3+1], k2 = kp[xm*3+2];
      float s = rh + rw[xm];
      s = fmaf(q0, k0.x, s); s = fmaf(q1, k0.y, s); s = fmaf(q2, k0.z, s); s = fmaf(q3, k0.w, s);
      s = fmaf(q4, k1.x, s); s = fmaf(q5, k1.y, s); s = fmaf(q6, k1.z, s); s = fmaf(q7, k1.w, s);
      s = fmaf(q8, k2.x, s); s = fmaf(q9, k2.y, s);
      float p = __expf(s);          // logits bounded ~O(0.5): no max-subtract needed
      l += p;
      float4 v0 = vp[xm*3], v1 = vp[xm*3+1], v2 = vp[xm*3+2];
      a0 = fmaf(p, v0.x, a0); a1 = fmaf(p, v0.y, a1); a2 = fmaf(p, v0.z, a2); a3 = fmaf(p, v0.w, a3);
      a4 = fmaf(p, v1.x, a4); a5 = fmaf(p, v1.y, a5); a6 = fmaf(p, v1.z, a6); a7 = fmaf(p, v1.w, a7);
      a8 = fmaf(p, v2.x, a8); a9 = fmaf(p, v2.y, a9);
    }
  }
  float inv = __frcp_rn(l);
  float* op = g_attn + (bh * 1024 + n) * 10;
  op[0]=a0*inv; op[1]=a1*inv; op[2]=a2*inv; op[3]=a3*inv; op[4]=a4*inv;
  op[5]=a5*inv; op[6]=a6*inv; op[7]=a7*inv; op[8]=a8*inv; op[9]=a9*inv;
}

// ---------------- K7: pooled attn + attno + fc ----------------
__global__ void final_kernel(const float* __restrict__ attno_w,
                             const float* __restrict__ attno_b,
                             const float* __restrict__ fc_w,
                             const float* __restrict__ fc_b,
                             float* __restrict__ out) {
  int b = blockIdx.x, tid = threadIdx.x;  // 256 threads
  int warp = tid >> 5, lane = tid & 31;
  __shared__ float mean_s[40], pa[40];
  // channel c' mean = mean of 1024 consecutive floats of (n,d)-flattened attn
  #pragma unroll
  for (int cc = 0; cc < 5; cc++) {
    int c = warp * 5 + cc;
    const float* p = g_attn + b * 40960 + c * 1024;
    float s = 0.f;
    for (int j = lane; j < 1024; j += 32) s += p[j];
    s = wred(s);
    if (lane == 0) mean_s[c] = s * (1.f / 1024.f);
  }
  __syncthreads();
  if (tid < 40) {
    float acc = __ldg(&attno_b[tid]);
    #pragma unroll 4
    for (int c = 0; c < 40; c++) acc = fmaf(__ldg(&attno_w[tid * 40 + c]), mean_s[c], acc);
    pa[tid] = acc;
  }
  __syncthreads();
  if (tid < 100) {
    float acc = __ldg(&fc_b[tid]);
    const float* wp = fc_w + tid * 128;
    #pragma unroll 4
    for (int c = 0; c < 88; c++) acc = fmaf(__ldg(&wp[c]), g_pooled[b * 88 + c], acc);
    #pragma unroll 4
    for (int c = 0; c < 40; c++) acc = fmaf(__ldg(&wp[88 + c]), pa[c], acc);
    out[b * 100 + tid] = acc;
  }
}

// ---------------- launch ----------------
extern "C" void kernel_launch(void* const* d_in, const int* in_sizes, int n_in,
                              void* d_out, int out_size) {
  const float* x         = (const float*)d_in[0];
  const float* conv1_w   = (const float*)d_in[1];
  const float* conv1_b   = (const float*)d_in[2];
  const float* bn1_g     = (const float*)d_in[3];
  const float* bn1_b     = (const float*)d_in[4];
  const float* convo_w   = (const float*)d_in[5];
  const float* convo_b   = (const float*)d_in[6];
  const float* qkv_w     = (const float*)d_in[7];
  const float* qkv_b     = (const float*)d_in[8];
  const float* attno_w   = (const float*)d_in[9];
  const float* attno_b   = (const float*)d_in[10];
  const float* key_rel_h = (const float*)d_in[11];
  const float* key_rel_w = (const float*)d_in[12];
  const float* fc_w      = (const float*)d_in[13];
  const float* fc_b      = (const float*)d_in[14];
  float* out = (float*)d_out;

  cudaFuncSetAttribute(attn_kernel, cudaFuncAttributeMaxDynamicSharedMemorySize, ATTN_SMEM);

  conv1_kernel<<<dim3(4, 64, 16), 256>>>(x, conv1_w, conv1_b);
  bnstats_kernel<<<64, 256>>>(bn1_g, bn1_b);
  bnrelu_kernel<<<dim3(64, 16), 1024>>>();
  poolconv_kernel<<<16, 96>>>(convo_w, convo_b);
  qkv_kernel<<<dim3(1, 15, 16), 256>>>(qkv_w, qkv_b);
  attn_kernel<<<dim3(8, 4, 16), 128, ATTN_SMEM>>>(key_rel_h, key_rel_w);
  final_kernel<<<16, 256>>>(attno_w, attno_b, fc_w, fc_b, out);
}

// round 2
// speedup vs baseline: 1.5937x; 1.5937x over previous
#include <cuda_runtime.h>

typedef unsigned long long u64;

// ---------------- scratch (device globals; no allocation) ----------------
__device__ float g_pre[16*64*1024];     // conv1 out, then h (in-place)
__device__ float g_S[16*64*9];          // 9 shifted window sums per (b, in-ch)
__device__ float g_scale[64];
__device__ float g_bnbias[64];
__device__ float g_Q[16*4*1024*10];
__device__ float g_Kb[16*4*1024*10];
__device__ float g_Vb[16*4*1024*10];
__device__ float g_attn[16*4*1024*10];
__device__ float g_pooled[16*88];

__device__ __forceinline__ float wred(float v) {
  #pragma unroll
  for (int o = 16; o; o >>= 1) v += __shfl_down_sync(0xffffffffu, v, o);
  return v;
}

// ---- packed f32x2 helpers (sm_100+) ----
__device__ __forceinline__ u64 ffma2(u64 a, u64 b, u64 c) {
  u64 d; asm("fma.rn.f32x2 %0, %1, %2, %3;" : "=l"(d) : "l"(a), "l"(b), "l"(c)); return d;
}
__device__ __forceinline__ u64 fmul2(u64 a, u64 b) {
  u64 d; asm("mul.rn.f32x2 %0, %1, %2;" : "=l"(d) : "l"(a), "l"(b)); return d;
}
__device__ __forceinline__ u64 pack2(float lo, float hi) {
  u64 r; asm("mov.b64 %0, {%1, %2};" : "=l"(r) : "f"(lo), "f"(hi)); return r;
}
__device__ __forceinline__ float2 unpack2(u64 v) {
  float lo, hi; asm("mov.b64 {%0, %1}, %2;" : "=f"(lo), "=f"(hi) : "l"(v));
  return make_float2(lo, hi);
}

union F4U { float4 f4; ulonglong2 u2; };
union F2U { float2 f2; u64 u; };

// ---------------- K1: conv1 3x3 (3->64), SAME ----------------
__global__ void conv1_kernel(const float* __restrict__ x,
                             const float* __restrict__ w,
                             const float* __restrict__ bias) {
  int p = blockIdx.x * 256 + threadIdx.x;   // pixel 0..1023
  int oc = blockIdx.y, b = blockIdx.z;
  int y = p >> 5, xx = p & 31;
  float acc = __ldg(&bias[oc]);
  const float* wp = w + oc * 27;
  #pragma unroll
  for (int ic = 0; ic < 3; ic++) {
    const float* xp = x + (b * 3 + ic) * 1024;
    #pragma unroll
    for (int ky = 0; ky < 3; ky++) {
      int iy = y + ky - 1;
      if (iy < 0 || iy > 31) continue;
      #pragma unroll
      for (int kx = 0; kx < 3; kx++) {
        int ix = xx + kx - 1;
        if (ix < 0 || ix > 31) continue;
        acc = fmaf(__ldg(&xp[iy * 32 + ix]), __ldg(&wp[ic * 9 + ky * 3 + kx]), acc);
      }
    }
  }
  g_pre[(b * 64 + oc) * 1024 + p] = acc;
}

// ---------------- K2: BN batch stats -> scale/bias ----------------
__global__ void bnstats_kernel(const float* __restrict__ gamma,
                               const float* __restrict__ beta) {
  int c = blockIdx.x, tid = threadIdx.x;
  float s = 0.f, sq = 0.f;
  #pragma unroll 4
  for (int j = tid; j < 16 * 1024; j += 256) {
    int b = j >> 10, p = j & 1023;
    float v = g_pre[(b * 64 + c) * 1024 + p];
    s += v; sq = fmaf(v, v, sq);
  }
  s = wred(s); sq = wred(sq);
  __shared__ float ss[8], s2[8];
  int warp = tid >> 5, lane = tid & 31;
  if (lane == 0) { ss[warp] = s; s2[warp] = sq; }
  __syncthreads();
  if (tid == 0) {
    float S = 0.f, Q = 0.f;
    #pragma unroll
    for (int i = 0; i < 8; i++) { S += ss[i]; Q += s2[i]; }
    float mean = S * (1.f / 16384.f);
    float var  = Q * (1.f / 16384.f) - mean * mean;
    float sc = __ldg(&gamma[c]) * rsqrtf(var + 1e-5f);
    g_scale[c]  = sc;
    g_bnbias[c] = __ldg(&beta[c]) - mean * sc;
  }
}

// ---------------- K3: BN apply + relu (in place) + 9 window sums ----------------
__global__ void bnrelu_kernel() {
  int c = blockIdx.x, b = blockIdx.y;
  int p = threadIdx.x;                  // 1024 threads
  int y = p >> 5, xx = p & 31;
  int idx = (b * 64 + c) * 1024 + p;
  float v = fmaxf(fmaf(g_pre[idx], g_scale[c], g_bnbias[c]), 0.f);
  g_pre[idx] = v;

  float t = v;
  float r0  = (y == 0)  ? v : 0.f;
  float r31 = (y == 31) ? v : 0.f;
  float c0  = (xx == 0)  ? v : 0.f;
  float c31 = (xx == 31) ? v : 0.f;

  __shared__ float red[32][5];
  __shared__ float corn[4];
  if (p == 0)    corn[0] = v;
  if (p == 31)   corn[1] = v;
  if (p == 992)  corn[2] = v;
  if (p == 1023) corn[3] = v;

  t = wred(t); r0 = wred(r0); r31 = wred(r31); c0 = wred(c0); c31 = wred(c31);
  int warp = p >> 5, lane = p & 31;
  if (lane == 0) { red[warp][0]=t; red[warp][1]=r0; red[warp][2]=r31; red[warp][3]=c0; red[warp][4]=c31; }
  __syncthreads();
  if (p < 32) {
    float a0 = red[p][0], a1 = red[p][1], a2 = red[p][2], a3 = red[p][3], a4 = red[p][4];
    a0 = wred(a0); a1 = wred(a1); a2 = wred(a2); a3 = wred(a3); a4 = wred(a4);
    if (p == 0) {
      float T = a0, R0 = a1, R31 = a2, C0 = a3, C31 = a4;
      float* Sp = g_S + (b * 64 + c) * 9;
      Sp[0] = T - R31 - C31 + corn[3];
      Sp[1] = T - R31;
      Sp[2] = T - R31 - C0 + corn[2];
      Sp[3] = T - C31;
      Sp[4] = T;
      Sp[5] = T - C0;
      Sp[6] = T - R0 - C31 + corn[1];
      Sp[7] = T - R0;
      Sp[8] = T - R0 - C0 + corn[0];
    }
  }
}

// ---------------- K4: pooled conv_out via window sums (warp per channel) ----------------
__global__ void poolconv_kernel(const float* __restrict__ w,
                                const float* __restrict__ cb) {
  int b = blockIdx.y;
  int oc = blockIdx.x * 8 + (threadIdx.x >> 5);
  int lane = threadIdx.x & 31;
  __shared__ float Ssm[576];
  for (int i = threadIdx.x; i < 576; i += 256) Ssm[i] = g_S[b * 576 + i];
  __syncthreads();
  float acc = 0.f;
  const float* wp = w + oc * 576;
  #pragma unroll
  for (int i = lane; i < 576; i += 32) acc = fmaf(__ldg(&wp[i]), Ssm[i], acc);
  acc = wred(acc);
  if (lane == 0) g_pooled[b * 88 + oc] = __ldg(&cb[oc]) + acc * (1.f / 1024.f);
}

// ---------------- K5: qkv 1x1 conv -> Q (scaled), K, V [bh][n][10] ----------------
__global__ void qkv_kernel(const float* __restrict__ w,
                           const float* __restrict__ bias) {
  int tid = threadIdx.x;        // 256
  int b = blockIdx.z;
  int o0 = blockIdx.y * 8;      // 15 groups of 8 output channels
  __shared__ float ws[512];
  __shared__ float bs[8];
  for (int i = tid; i < 512; i += 256) ws[i] = w[o0 * 64 + i];
  if (tid < 8) bs[tid] = bias[o0 + tid];
  __syncthreads();
  int n0 = tid * 4;
  float4 acc[8];
  #pragma unroll
  for (int u = 0; u < 8; u++) { float bv = bs[u]; acc[u] = make_float4(bv, bv, bv, bv); }
  const float* hp = g_pre + b * 64 * 1024 + n0;
  #pragma unroll 4
  for (int i = 0; i < 64; i++) {
    float4 hv = *(const float4*)(hp + i * 1024);
    #pragma unroll
    for (int u = 0; u < 8; u++) {
      float wv = ws[u * 64 + i];
      acc[u].x = fmaf(wv, hv.x, acc[u].x);
      acc[u].y = fmaf(wv, hv.y, acc[u].y);
      acc[u].z = fmaf(wv, hv.z, acc[u].z);
      acc[u].w = fmaf(wv, hv.w, acc[u].w);
    }
  }
  #pragma unroll
  for (int u = 0; u < 8; u++) {
    int o = o0 + u;
    int which = o / 40;
    int r = o - which * 40;
    int head = r / 10, d = r - head * 10;
    float* dst = (which == 0) ? g_Q : ((which == 1) ? g_Kb : g_Vb);
    float mul = (which == 0) ? 0.31622776601683794f : 1.f;   // dkh^-0.5
    float* pb = dst + ((b * 4 + head) * 1024) * 10 + d;
    pb[(n0 + 0) * 10] = acc[u].x * mul;
    pb[(n0 + 1) * 10] = acc[u].y * mul;
    pb[(n0 + 2) * 10] = acc[u].z * mul;
    pb[(n0 + 3) * 10] = acc[u].w * mul;
  }
}

// ---------------- K6: attention (f32x2 packed), 8 query rows / block ----------------
#define ATTN_SMEM ((12288 + 12288 + 640) * 4)

__global__ void __launch_bounds__(256) attn_kernel(const float* __restrict__ krh,
                                                   const float* __restrict__ krw) {
  extern __shared__ float sm[];
  float* Ks = sm;             // [m][12] padded
  float* Vs = sm + 12288;     // [m][12] padded
  float* Hs = sm + 24576;     // key_rel_h 63*10
  int b = blockIdx.z, h = blockIdx.y;
  int bh = b * 4 + h;
  int tid = threadIdx.x;
  int warp = tid >> 5, lane = tid & 31;
  const float* Kp = g_Kb + bh * 10240;
  const float* Vp = g_Vb + bh * 10240;
  for (int i = tid; i < 12288; i += 256) {
    int m = i / 12, d = i - m * 12;
    float kv = 0.f, vv = 0.f;
    if (d < 10) { kv = Kp[m * 10 + d]; vv = Vp[m * 10 + d]; }
    Ks[i] = kv; Vs[i] = vv;
  }
  for (int i = tid; i < 630; i += 256) Hs[i] = krh[i];

  int yq = blockIdx.x * 8 + warp;   // warp = one query row
  int xq = lane;
  int n = yq * 32 + xq;
  const float* qp = g_Q + (bh * 1024 + n) * 10;
  float q0 = qp[0], q1 = qp[1], q2 = qp[2], q3 = qp[3], q4 = qp[4];
  float q5 = qp[5], q6 = qp[6], q7 = qp[7], q8 = qp[8], q9 = qp[9];
  u64 Q01 = pack2(q0, q1), Q23 = pack2(q2, q3), Q45 = pack2(q4, q5),
      Q67 = pack2(q6, q7), Q89 = pack2(q8, q9);

  // rw[xm] = q . key_rel_w[xm - xq + 31]
  float rw[32];
  #pragma unroll
  for (int xm = 0; xm < 32; xm++) {
    const float* kr = krw + (xm - xq + 31) * 10;
    float s = q0 * __ldg(&kr[0]);
    s = fmaf(q1, __ldg(&kr[1]), s); s = fmaf(q2, __ldg(&kr[2]), s);
    s = fmaf(q3, __ldg(&kr[3]), s); s = fmaf(q4, __ldg(&kr[4]), s);
    s = fmaf(q5, __ldg(&kr[5]), s); s = fmaf(q6, __ldg(&kr[6]), s);
    s = fmaf(q7, __ldg(&kr[7]), s); s = fmaf(q8, __ldg(&kr[8]), s);
    s = fmaf(q9, __ldg(&kr[9]), s);
    rw[xm] = s;
  }
  __syncthreads();

  u64 a01 = 0ull, a23 = 0ull, a45 = 0ull, a67 = 0ull, a89 = 0ull;
  float l = 0.f;
  #pragma unroll 1
  for (int ym = 0; ym < 32; ym++) {
    const float* kh = Hs + (ym - yq + 31) * 10;   // broadcast (yq const per warp)
    float rh = q0 * kh[0];
    rh = fmaf(q1, kh[1], rh); rh = fmaf(q2, kh[2], rh);
    rh = fmaf(q3, kh[3], rh); rh = fmaf(q4, kh[4], rh);
    rh = fmaf(q5, kh[5], rh); rh = fmaf(q6, kh[6], rh);
    rh = fmaf(q7, kh[7], rh); rh = fmaf(q8, kh[8], rh);
    rh = fmaf(q9, kh[9], rh);
    const float* kr = Ks + ym * 384;
    const float* vr = Vs + ym * 384;
    #pragma unroll
    for (int xm = 0; xm < 32; xm++) {
      F4U ka; ka.f4 = *(const float4*)(kr + xm * 12);
      F4U kb; kb.f4 = *(const float4*)(kr + xm * 12 + 4);
      F2U kc; kc.f2 = *(const float2*)(kr + xm * 12 + 8);
      // init packs the rank-1 biases; horizontal combine absorbs them
      u64 s2 = ffma2(Q01, ka.u2.x, pack2(rh, rw[xm]));
      s2 = ffma2(Q23, ka.u2.y, s2);
      s2 = ffma2(Q45, kb.u2.x, s2);
      s2 = ffma2(Q67, kb.u2.y, s2);
      s2 = ffma2(Q89, kc.u, s2);
      float2 sp = unpack2(s2);
      float p = __expf(sp.x + sp.y);   // logits bounded ~O(0.5): no max-subtract
      l += p;
      u64 p2 = pack2(p, p);
      F4U va; va.f4 = *(const float4*)(vr + xm * 12);
      F4U vb; vb.f4 = *(const float4*)(vr + xm * 12 + 4);
      F2U vc; vc.f2 = *(const float2*)(vr + xm * 12 + 8);
      a01 = ffma2(p2, va.u2.x, a01);
      a23 = ffma2(p2, va.u2.y, a23);
      a45 = ffma2(p2, vb.u2.x, a45);
      a67 = ffma2(p2, vb.u2.y, a67);
      a89 = ffma2(p2, vc.u, a89);
    }
  }
  float inv = __frcp_rn(l);
  u64 inv2 = pack2(inv, inv);
  u64* op = (u64*)(g_attn + (bh * 1024 + n) * 10);
  op[0] = fmul2(a01, inv2);
  op[1] = fmul2(a23, inv2);
  op[2] = fmul2(a45, inv2);
  op[3] = fmul2(a67, inv2);
  op[4] = fmul2(a89, inv2);
}

// ---------------- K7: pooled attn + attno + fc ----------------
__global__ void final_kernel(const float* __restrict__ attno_w,
                             const float* __restrict__ attno_b,
                             const float* __restrict__ fc_w,
                             const float* __restrict__ fc_b,
                             float* __restrict__ out) {
  int b = blockIdx.x, tid = threadIdx.x;  // 256 threads
  int warp = tid >> 5, lane = tid & 31;
  __shared__ float mean_s[40], pa[40];
  #pragma unroll
  for (int cc = 0; cc < 5; cc++) {
    int c = warp * 5 + cc;
    const float* p = g_attn + b * 40960 + c * 1024;
    float s = 0.f;
    #pragma unroll 4
    for (int j = lane; j < 1024; j += 32) s += p[j];
    s = wred(s);
    if (lane == 0) mean_s[c] = s * (1.f / 1024.f);
  }
  __syncthreads();
  if (tid < 40) {
    float acc = __ldg(&attno_b[tid]);
    #pragma unroll 4
    for (int c = 0; c < 40; c++) acc = fmaf(__ldg(&attno_w[tid * 40 + c]), mean_s[c], acc);
    pa[tid] = acc;
  }
  __syncthreads();
  if (tid < 100) {
    float acc = __ldg(&fc_b[tid]);
    const float* wp = fc_w + tid * 128;
    #pragma unroll 4
    for (int c = 0; c < 88; c++) acc = fmaf(__ldg(&wp[c]), g_pooled[b * 88 + c], acc);
    #pragma unroll 4
    for (int c = 0; c < 40; c++) acc = fmaf(__ldg(&wp[88 + c]), pa[c], acc);
    out[b * 100 + tid] = acc;
  }
}

// ---------------- launch ----------------
extern "C" void kernel_launch(void* const* d_in, const int* in_sizes, int n_in,
                              void* d_out, int out_size) {
  const float* x         = (const float*)d_in[0];
  const float* conv1_w   = (const float*)d_in[1];
  const float* conv1_b   = (const float*)d_in[2];
  const float* bn1_g     = (const float*)d_in[3];
  const float* bn1_b     = (const float*)d_in[4];
  const float* convo_w   = (const float*)d_in[5];
  const float* convo_b   = (const float*)d_in[6];
  const float* qkv_w     = (const float*)d_in[7];
  const float* qkv_b     = (const float*)d_in[8];
  const float* attno_w   = (const float*)d_in[9];
  const float* attno_b   = (const float*)d_in[10];
  const float* key_rel_h = (const float*)d_in[11];
  const float* key_rel_w = (const float*)d_in[12];
  const float* fc_w      = (const float*)d_in[13];
  const float* fc_b      = (const float*)d_in[14];
  float* out = (float*)d_out;

  cudaFuncSetAttribute(attn_kernel, cudaFuncAttributeMaxDynamicSharedMemorySize, ATTN_SMEM);

  conv1_kernel<<<dim3(4, 64, 16), 256>>>(x, conv1_w, conv1_b);
  bnstats_kernel<<<64, 256>>>(bn1_g, bn1_b);
  bnrelu_kernel<<<dim3(64, 16), 1024>>>();
  poolconv_kernel<<<dim3(11, 16), 256>>>(convo_w, convo_b);
  qkv_kernel<<<dim3(1, 15, 16), 256>>>(qkv_w, qkv_b);
  attn_kernel<<<dim3(4, 4, 16), 256, ATTN_SMEM>>>(key_rel_h, key_rel_w);
  final_kernel<<<16, 256>>>(attno_w, attno_b, fc_w, fc_b, out);
}

// round 3
// speedup vs baseline: 1.7800x; 1.1169x over previous
#include <cuda_runtime.h>

typedef unsigned long long u64;

// ---------------- scratch (device globals; no allocation) ----------------
__device__ float g_pre[16*64*1024];     // conv1 out, then h (in-place)
__device__ float g_S[16*64*9];          // 9 shifted window sums per (b, in-ch)
__device__ float g_scale[64];
__device__ float g_bnbias[64];
__device__ float g_Q[16*4*1024*10];
__device__ float g_Kb[16*4*1024*10];
__device__ float g_Vb[16*4*1024*10];
__device__ float g_attn[16*4*1024*10];
__device__ float g_pooled[16*88];

__device__ __forceinline__ float wred(float v) {
  #pragma unroll
  for (int o = 16; o; o >>= 1) v += __shfl_down_sync(0xffffffffu, v, o);
  return v;
}

// ---- packed f32x2 helpers (sm_100+) ----
__device__ __forceinline__ u64 ffma2(u64 a, u64 b, u64 c) {
  u64 d; asm("fma.rn.f32x2 %0, %1, %2, %3;" : "=l"(d) : "l"(a), "l"(b), "l"(c)); return d;
}
__device__ __forceinline__ u64 fmul2(u64 a, u64 b) {
  u64 d; asm("mul.rn.f32x2 %0, %1, %2;" : "=l"(d) : "l"(a), "l"(b)); return d;
}
__device__ __forceinline__ u64 pack2(float lo, float hi) {
  u64 r; asm("mov.b64 %0, {%1, %2};" : "=l"(r) : "f"(lo), "f"(hi)); return r;
}
__device__ __forceinline__ float2 unpack2(u64 v) {
  float lo, hi; asm("mov.b64 {%0, %1}, %2;" : "=f"(lo), "=f"(hi) : "l"(v));
  return make_float2(lo, hi);
}
__device__ __forceinline__ float ex2f(float x) {
  float y; asm("ex2.approx.f32 %0, %1;" : "=f"(y) : "f"(x)); return y;
}

union F4U { float4 f4; ulonglong2 u2; };
union F2U { float2 f2; u64 u; };

// ---------------- K1: conv1 3x3 (3->64), SAME — 4 pixels/thread ----------------
__global__ void __launch_bounds__(256) conv1_kernel(const float* __restrict__ x,
                                                    const float* __restrict__ w,
                                                    const float* __restrict__ bias) {
  int t = threadIdx.x;
  int oc = blockIdx.x, b = blockIdx.y;
  int p0 = t * 4;
  int y = p0 >> 5, x0 = p0 & 31;   // x0 in {0,4,...,28}
  float w_[27];
  #pragma unroll
  for (int i = 0; i < 27; i++) w_[i] = __ldg(&w[oc * 27 + i]);
  float bv = __ldg(&bias[oc]);
  float a0 = bv, a1 = bv, a2 = bv, a3 = bv;
  #pragma unroll
  for (int ic = 0; ic < 3; ic++) {
    const float* base = x + (b * 3 + ic) * 1024;
    #pragma unroll
    for (int ky = 0; ky < 3; ky++) {
      int iy = y + ky - 1;
      if (iy < 0 || iy > 31) continue;
      const float* row = base + iy * 32;
      float r[6];
      #pragma unroll
      for (int dx = 0; dx < 6; dx++) {
        int c = x0 - 1 + dx;
        r[dx] = (c >= 0 && c < 32) ? __ldg(&row[c]) : 0.f;
      }
      #pragma unroll
      for (int kx = 0; kx < 3; kx++) {
        float wv = w_[ic * 9 + ky * 3 + kx];
        a0 = fmaf(wv, r[kx],     a0);
        a1 = fmaf(wv, r[kx + 1], a1);
        a2 = fmaf(wv, r[kx + 2], a2);
        a3 = fmaf(wv, r[kx + 3], a3);
      }
    }
  }
  *(float4*)(g_pre + (b * 64 + oc) * 1024 + p0) = make_float4(a0, a1, a2, a3);
}

// ---------------- K2: BN batch stats -> scale/bias ----------------
__global__ void bnstats_kernel(const float* __restrict__ gamma,
                               const float* __restrict__ beta) {
  int c = blockIdx.x, tid = threadIdx.x;
  float s = 0.f, sq = 0.f;
  #pragma unroll 4
  for (int j = tid; j < 16 * 1024; j += 256) {
    int b = j >> 10, p = j & 1023;
    float v = g_pre[(b * 64 + c) * 1024 + p];
    s += v; sq = fmaf(v, v, sq);
  }
  s = wred(s); sq = wred(sq);
  __shared__ float ss[8], s2[8];
  int warp = tid >> 5, lane = tid & 31;
  if (lane == 0) { ss[warp] = s; s2[warp] = sq; }
  __syncthreads();
  if (tid == 0) {
    float S = 0.f, Q = 0.f;
    #pragma unroll
    for (int i = 0; i < 8; i++) { S += ss[i]; Q += s2[i]; }
    float mean = S * (1.f / 16384.f);
    float var  = Q * (1.f / 16384.f) - mean * mean;
    float sc = __ldg(&gamma[c]) * rsqrtf(var + 1e-5f);
    g_scale[c]  = sc;
    g_bnbias[c] = __ldg(&beta[c]) - mean * sc;
  }
}

// ---------------- K3: BN apply + relu (in place) + 9 window sums ----------------
__global__ void bnrelu_kernel() {
  int c = blockIdx.x, b = blockIdx.y;
  int p = threadIdx.x;                  // 1024 threads
  int y = p >> 5, xx = p & 31;
  int idx = (b * 64 + c) * 1024 + p;
  float v = fmaxf(fmaf(g_pre[idx], g_scale[c], g_bnbias[c]), 0.f);
  g_pre[idx] = v;

  float t = v;
  float r0  = (y == 0)  ? v : 0.f;
  float r31 = (y == 31) ? v : 0.f;
  float c0  = (xx == 0)  ? v : 0.f;
  float c31 = (xx == 31) ? v : 0.f;

  __shared__ float red[32][5];
  __shared__ float corn[4];
  if (p == 0)    corn[0] = v;
  if (p == 31)   corn[1] = v;
  if (p == 992)  corn[2] = v;
  if (p == 1023) corn[3] = v;

  t = wred(t); r0 = wred(r0); r31 = wred(r31); c0 = wred(c0); c31 = wred(c31);
  int warp = p >> 5, lane = p & 31;
  if (lane == 0) { red[warp][0]=t; red[warp][1]=r0; red[warp][2]=r31; red[warp][3]=c0; red[warp][4]=c31; }
  __syncthreads();
  if (p < 32) {
    float a0 = red[p][0], a1 = red[p][1], a2 = red[p][2], a3 = red[p][3], a4 = red[p][4];
    a0 = wred(a0); a1 = wred(a1); a2 = wred(a2); a3 = wred(a3); a4 = wred(a4);
    if (p == 0) {
      float T = a0, R0 = a1, R31 = a2, C0 = a3, C31 = a4;
      float* Sp = g_S + (b * 64 + c) * 9;
      Sp[0] = T - R31 - C31 + corn[3];
      Sp[1] = T - R31;
      Sp[2] = T - R31 - C0 + corn[2];
      Sp[3] = T - C31;
      Sp[4] = T;
      Sp[5] = T - C0;
      Sp[6] = T - R0 - C31 + corn[1];
      Sp[7] = T - R0;
      Sp[8] = T - R0 - C0 + corn[0];
    }
  }
}

// ---------------- K4: pooled conv_out via window sums (warp per channel) ----------------
__global__ void poolconv_kernel(const float* __restrict__ w,
                                const float* __restrict__ cb) {
  int b = blockIdx.y;
  int oc = blockIdx.x * 8 + (threadIdx.x >> 5);
  int lane = threadIdx.x & 31;
  __shared__ float Ssm[576];
  for (int i = threadIdx.x; i < 576; i += 256) Ssm[i] = g_S[b * 576 + i];
  __syncthreads();
  float acc = 0.f;
  const float* wp = w + oc * 576;
  #pragma unroll
  for (int i = lane; i < 576; i += 32) acc = fmaf(__ldg(&wp[i]), Ssm[i], acc);
  acc = wred(acc);
  if (lane == 0) g_pooled[b * 88 + oc] = __ldg(&cb[oc]) + acc * (1.f / 1024.f);
}

// ---------------- K5: qkv 1x1 conv -> Q (scaled by dkh^-0.5 * log2e), K, V ----------------
__global__ void __launch_bounds__(256) qkv_kernel(const float* __restrict__ w,
                                                  const float* __restrict__ bias) {
  int tid = threadIdx.x;        // 256
  int b = blockIdx.z;
  int o0 = blockIdx.y * 8;      // 15 groups of 8 output channels
  __shared__ float ws[512];
  __shared__ float bs[8];
  for (int i = tid; i < 512; i += 256) ws[i] = w[o0 * 64 + i];
  if (tid < 8) bs[tid] = bias[o0 + tid];
  __syncthreads();
  int n0 = tid * 4;
  float4 acc[8];
  #pragma unroll
  for (int u = 0; u < 8; u++) { float bv = bs[u]; acc[u] = make_float4(bv, bv, bv, bv); }
  const float* hp = g_pre + b * 64 * 1024 + n0;
  #pragma unroll 4
  for (int i = 0; i < 64; i++) {
    float4 hv = *(const float4*)(hp + i * 1024);
    #pragma unroll
    for (int u = 0; u < 8; u++) {
      float wv = ws[u * 64 + i];
      acc[u].x = fmaf(wv, hv.x, acc[u].x);
      acc[u].y = fmaf(wv, hv.y, acc[u].y);
      acc[u].z = fmaf(wv, hv.z, acc[u].z);
      acc[u].w = fmaf(wv, hv.w, acc[u].w);
    }
  }
  // Q gets dkh^-0.5 * log2(e) folded in: softmax uses ex2 of (log2e * logits),
  // exact since all logit terms (qk, rh, rw) are linear in q.
  const float QMUL = 0.31622776601683794f * 1.4426950408889634f;
  #pragma unroll
  for (int u = 0; u < 8; u++) {
    int o = o0 + u;
    int which = o / 40;
    int r = o - which * 40;
    int head = r / 10, d = r - head * 10;
    float* dst = (which == 0) ? g_Q : ((which == 1) ? g_Kb : g_Vb);
    float mul = (which == 0) ? QMUL : 1.f;
    float* pb = dst + ((b * 4 + head) * 1024) * 10 + d;
    pb[(n0 + 0) * 10] = acc[u].x * mul;
    pb[(n0 + 1) * 10] = acc[u].y * mul;
    pb[(n0 + 2) * 10] = acc[u].z * mul;
    pb[(n0 + 3) * 10] = acc[u].w * mul;
  }
}

// ---------------- K6: attention (f32x2 packed), 8 query rows / block ----------------
#define ATTN_SMEM ((12288 + 12288 + 640) * 4)

__global__ void __launch_bounds__(256, 2) attn_kernel(const float* __restrict__ krh,
                                                      const float* __restrict__ krw) {
  extern __shared__ float sm[];
  float* Ks = sm;             // [m][12] padded
  float* Vs = sm + 12288;     // [m][12] padded
  float* Hs = sm + 24576;     // key_rel_h 63*10
  int b = blockIdx.z, h = blockIdx.y;
  int bh = b * 4 + h;
  int tid = threadIdx.x;
  int warp = tid >> 5, lane = tid & 31;
  const float* Kp = g_Kb + bh * 10240;
  const float* Vp = g_Vb + bh * 10240;
  for (int i = tid; i < 12288; i += 256) {
    int m = i / 12, d = i - m * 12;
    float kv = 0.f, vv = 0.f;
    if (d < 10) { kv = Kp[m * 10 + d]; vv = Vp[m * 10 + d]; }
    Ks[i] = kv; Vs[i] = vv;
  }
  for (int i = tid; i < 630; i += 256) Hs[i] = krh[i];

  int yq = blockIdx.x * 8 + warp;   // warp = one query row
  int xq = lane;
  int n = yq * 32 + xq;
  const float* qp = g_Q + (bh * 1024 + n) * 10;   // pre-scaled by dkh^-.5*log2e
  float q0 = qp[0], q1 = qp[1], q2 = qp[2], q3 = qp[3], q4 = qp[4];
  float q5 = qp[5], q6 = qp[6], q7 = qp[7], q8 = qp[8], q9 = qp[9];
  u64 Q01 = pack2(q0, q1), Q23 = pack2(q2, q3), Q45 = pack2(q4, q5),
      Q67 = pack2(q6, q7), Q89 = pack2(q8, q9);

  // rw[xm] = q . key_rel_w[xm - xq + 31]   (already in log2e domain)
  float rw[32];
  #pragma unroll
  for (int xm = 0; xm < 32; xm++) {
    const float* kr = krw + (xm - xq + 31) * 10;
    float s = q0 * __ldg(&kr[0]);
    s = fmaf(q1, __ldg(&kr[1]), s); s = fmaf(q2, __ldg(&kr[2]), s);
    s = fmaf(q3, __ldg(&kr[3]), s); s = fmaf(q4, __ldg(&kr[4]), s);
    s = fmaf(q5, __ldg(&kr[5]), s); s = fmaf(q6, __ldg(&kr[6]), s);
    s = fmaf(q7, __ldg(&kr[7]), s); s = fmaf(q8, __ldg(&kr[8]), s);
    s = fmaf(q9, __ldg(&kr[9]), s);
    rw[xm] = s;
  }
  __syncthreads();

  u64 a01 = 0ull, a23 = 0ull, a45 = 0ull, a67 = 0ull, a89 = 0ull;
  float l = 0.f;
  #pragma unroll 1
  for (int ym = 0; ym < 32; ym++) {
    const float* kh = Hs + (ym - yq + 31) * 10;   // broadcast (yq const per warp)
    float rh = q0 * kh[0];
    rh = fmaf(q1, kh[1], rh); rh = fmaf(q2, kh[2], rh);
    rh = fmaf(q3, kh[3], rh); rh = fmaf(q4, kh[4], rh);
    rh = fmaf(q5, kh[5], rh); rh = fmaf(q6, kh[6], rh);
    rh = fmaf(q7, kh[7], rh); rh = fmaf(q8, kh[8], rh);
    rh = fmaf(q9, kh[9], rh);
    const float* kr = Ks + ym * 384;
    const float* vr = Vs + ym * 384;
    #pragma unroll
    for (int xm = 0; xm < 32; xm++) {
      F4U ka; ka.f4 = *(const float4*)(kr + xm * 12);
      F4U kb; kb.f4 = *(const float4*)(kr + xm * 12 + 4);
      F2U kc; kc.f2 = *(const float2*)(kr + xm * 12 + 8);
      u64 s2 = ffma2(Q01, ka.u2.x, pack2(rh, rw[xm]));
      s2 = ffma2(Q23, ka.u2.y, s2);
      s2 = ffma2(Q45, kb.u2.x, s2);
      s2 = ffma2(Q67, kb.u2.y, s2);
      s2 = ffma2(Q89, kc.u, s2);
      float2 sp = unpack2(s2);
      float p = ex2f(sp.x + sp.y);     // logits tiny; no max-subtract needed
      l += p;
      u64 p2 = pack2(p, p);
      F4U va; va.f4 = *(const float4*)(vr + xm * 12);
      F4U vb; vb.f4 = *(const float4*)(vr + xm * 12 + 4);
      F2U vc; vc.f2 = *(const float2*)(vr + xm * 12 + 8);
      a01 = ffma2(p2, va.u2.x, a01);
      a23 = ffma2(p2, va.u2.y, a23);
      a45 = ffma2(p2, vb.u2.x, a45);
      a67 = ffma2(p2, vb.u2.y, a67);
      a89 = ffma2(p2, vc.u, a89);
    }
  }
  float inv = __frcp_rn(l);
  u64 inv2 = pack2(inv, inv);
  u64* op = (u64*)(g_attn + (bh * 1024 + n) * 10);
  op[0] = fmul2(a01, inv2);
  op[1] = fmul2(a23, inv2);
  op[2] = fmul2(a45, inv2);
  op[3] = fmul2(a67, inv2);
  op[4] = fmul2(a89, inv2);
}

// ---------------- K7: pooled attn + attno + fc ----------------
__global__ void final_kernel(const float* __restrict__ attno_w,
                             const float* __restrict__ attno_b,
                             const float* __restrict__ fc_w,
                             const float* __restrict__ fc_b,
                             float* __restrict__ out) {
  int b = blockIdx.x, tid = threadIdx.x;  // 256 threads
  int warp = tid >> 5, lane = tid & 31;
  __shared__ float mean_s[40], pa[40];
  #pragma unroll
  for (int cc = 0; cc < 5; cc++) {
    int c = warp * 5 + cc;
    const float* p = g_attn + b * 40960 + c * 1024;
    float s = 0.f;
    #pragma unroll 4
    for (int j = lane; j < 1024; j += 32) s += p[j];
    s = wred(s);
    if (lane == 0) mean_s[c] = s * (1.f / 1024.f);
  }
  __syncthreads();
  if (tid < 40) {
    float acc = __ldg(&attno_b[tid]);
    #pragma unroll 4
    for (int c = 0; c < 40; c++) acc = fmaf(__ldg(&attno_w[tid * 40 + c]), mean_s[c], acc);
    pa[tid] = acc;
  }
  __syncthreads();
  if (tid < 100) {
    float acc = __ldg(&fc_b[tid]);
    const float* wp = fc_w + tid * 128;
    #pragma unroll 4
    for (int c = 0; c < 88; c++) acc = fmaf(__ldg(&wp[c]), g_pooled[b * 88 + c], acc);
    #pragma unroll 4
    for (int c = 0; c < 40; c++) acc = fmaf(__ldg(&wp[88 + c]), pa[c], acc);
    out[b * 100 + tid] = acc;
  }
}

// ---------------- launch ----------------
extern "C" void kernel_launch(void* const* d_in, const int* in_sizes, int n_in,
                              void* d_out, int out_size) {
  const float* x         = (const float*)d_in[0];
  const float* conv1_w   = (const float*)d_in[1];
  const float* conv1_b   = (const float*)d_in[2];
  const float* bn1_g     = (const float*)d_in[3];
  const float* bn1_b     = (const float*)d_in[4];
  const float* convo_w   = (const float*)d_in[5];
  const float* convo_b   = (const float*)d_in[6];
  const float* qkv_w     = (const float*)d_in[7];
  const float* qkv_b     = (const float*)d_in[8];
  const float* attno_w   = (const float*)d_in[9];
  const float* attno_b   = (const float*)d_in[10];
  const float* key_rel_h = (const float*)d_in[11];
  const float* key_rel_w = (const float*)d_in[12];
  const float* fc_w      = (const float*)d_in[13];
  const float* fc_b      = (const float*)d_in[14];
  float* out = (float*)d_out;

  cudaFuncSetAttribute(attn_kernel, cudaFuncAttributeMaxDynamicSharedMemorySize, ATTN_SMEM);

  conv1_kernel<<<dim3(64, 16), 256>>>(x, conv1_w, conv1_b);
  bnstats_kernel<<<64, 256>>>(bn1_g, bn1_b);
  bnrelu_kernel<<<dim3(64, 16), 1024>>>();
  poolconv_kernel<<<dim3(11, 16), 256>>>(convo_w, convo_b);
  qkv_kernel<<<dim3(1, 15, 16), 256>>>(qkv_w, qkv_b);
  attn_kernel<<<dim3(4, 4, 16), 256, ATTN_SMEM>>>(key_rel_h, key_rel_w);
  final_kernel<<<16, 256>>>(attno_w, attno_b, fc_w, fc_b, out);
}

// round 4
// speedup vs baseline: 1.8515x; 1.0402x over previous
#include <cuda_runtime.h>

typedef unsigned long long u64;

// ---------------- scratch (device globals; no allocation) ----------------
__device__ float g_pre[16*64*1024];     // conv1 out, then h (in-place)
__device__ float2 g_bstats[64*16];      // per (oc,b) partial {sum, sumsq}
__device__ float g_S[16*64*9];          // 9 shifted window sums per (b, in-ch)
__device__ float g_Q[16*4*1024*10];
__device__ float g_Kb[16*4*1024*10];
__device__ float g_Vb[16*4*1024*10];
__device__ float g_attn[16*4*1024*10];

__device__ __forceinline__ float wred(float v) {
  #pragma unroll
  for (int o = 16; o; o >>= 1) v += __shfl_down_sync(0xffffffffu, v, o);
  return v;
}

// ---- packed f32x2 helpers (sm_100+) ----
__device__ __forceinline__ u64 ffma2(u64 a, u64 b, u64 c) {
  u64 d; asm("fma.rn.f32x2 %0, %1, %2, %3;" : "=l"(d) : "l"(a), "l"(b), "l"(c)); return d;
}
__device__ __forceinline__ u64 fmul2(u64 a, u64 b) {
  u64 d; asm("mul.rn.f32x2 %0, %1, %2;" : "=l"(d) : "l"(a), "l"(b)); return d;
}
__device__ __forceinline__ u64 pack2(float lo, float hi) {
  u64 r; asm("mov.b64 %0, {%1, %2};" : "=l"(r) : "f"(lo), "f"(hi)); return r;
}
__device__ __forceinline__ float2 unpack2(u64 v) {
  float lo, hi; asm("mov.b64 {%0, %1}, %2;" : "=f"(lo), "=f"(hi) : "l"(v));
  return make_float2(lo, hi);
}
__device__ __forceinline__ float ex2f(float x) {
  float y; asm("ex2.approx.f32 %0, %1;" : "=f"(y) : "f"(x)); return y;
}

union F4U { float4 f4; ulonglong2 u2; };
union F2U { float2 f2; u64 u; };

__device__ __forceinline__ u64 ldf2(const float* p) {
  F2U t; t.f2 = *(const float2*)p; return t.u;
}

// ---------------- K0: conv1 3x3 (3->64) SAME + per-block BN partial stats ----------------
__global__ void __launch_bounds__(256) conv1_kernel(const float* __restrict__ x,
                                                    const float* __restrict__ w,
                                                    const float* __restrict__ bias) {
  int t = threadIdx.x;
  int oc = blockIdx.x, b = blockIdx.y;
  int p0 = t * 4;
  int y = p0 >> 5, x0 = p0 & 31;   // x0 in {0,4,...,28}
  float w_[27];
  #pragma unroll
  for (int i = 0; i < 27; i++) w_[i] = __ldg(&w[oc * 27 + i]);
  float bv = __ldg(&bias[oc]);
  float a0 = bv, a1 = bv, a2 = bv, a3 = bv;
  #pragma unroll
  for (int ic = 0; ic < 3; ic++) {
    const float* base = x + (b * 3 + ic) * 1024;
    #pragma unroll
    for (int ky = 0; ky < 3; ky++) {
      int iy = y + ky - 1;
      if (iy < 0 || iy > 31) continue;
      const float* row = base + iy * 32;
      float r[6];
      #pragma unroll
      for (int dx = 0; dx < 6; dx++) {
        int c = x0 - 1 + dx;
        r[dx] = (c >= 0 && c < 32) ? __ldg(&row[c]) : 0.f;
      }
      #pragma unroll
      for (int kx = 0; kx < 3; kx++) {
        float wv = w_[ic * 9 + ky * 3 + kx];
        a0 = fmaf(wv, r[kx],     a0);
        a1 = fmaf(wv, r[kx + 1], a1);
        a2 = fmaf(wv, r[kx + 2], a2);
        a3 = fmaf(wv, r[kx + 3], a3);
      }
    }
  }
  *(float4*)(g_pre + (b * 64 + oc) * 1024 + p0) = make_float4(a0, a1, a2, a3);

  // per-block partial stats (deterministic; no atomics)
  float s  = a0 + a1 + a2 + a3;
  float sq = fmaf(a0, a0, fmaf(a1, a1, fmaf(a2, a2, a3 * a3)));
  s = wred(s); sq = wred(sq);
  __shared__ float ss[8], s2m[8];
  int warp = t >> 5, lane = t & 31;
  if (lane == 0) { ss[warp] = s; s2m[warp] = sq; }
  __syncthreads();
  if (t == 0) {
    float S = 0.f, Q = 0.f;
    #pragma unroll
    for (int i = 0; i < 8; i++) { S += ss[i]; Q += s2m[i]; }
    g_bstats[oc * 16 + b] = make_float2(S, Q);
  }
}

// ---------------- K1: BN finalize + apply + relu (in place) + 9 window sums ----------------
__global__ void bnrelu_kernel(const float* __restrict__ gamma,
                              const float* __restrict__ beta) {
  int c = blockIdx.x, b = blockIdx.y;
  int p = threadIdx.x;                  // 1024 threads
  __shared__ float scb[2];
  if (p < 16) {
    float2 v = g_bstats[c * 16 + p];
    float s = v.x, q = v.y;
    #pragma unroll
    for (int o = 8; o; o >>= 1) {
      s += __shfl_down_sync(0xffffu, s, o, 16);
      q += __shfl_down_sync(0xffffu, q, o, 16);
    }
    if (p == 0) {
      float mean = s * (1.f / 16384.f);
      float var  = q * (1.f / 16384.f) - mean * mean;
      float sc = __ldg(&gamma[c]) * rsqrtf(var + 1e-5f);
      scb[0] = sc;
      scb[1] = __ldg(&beta[c]) - mean * sc;
    }
  }
  __syncthreads();

  int y = p >> 5, xx = p & 31;
  int idx = (b * 64 + c) * 1024 + p;
  float v = fmaxf(fmaf(g_pre[idx], scb[0], scb[1]), 0.f);
  g_pre[idx] = v;

  float t = v;
  float r0  = (y == 0)  ? v : 0.f;
  float r31 = (y == 31) ? v : 0.f;
  float c0  = (xx == 0)  ? v : 0.f;
  float c31 = (xx == 31) ? v : 0.f;

  __shared__ float red[32][5];
  __shared__ float corn[4];
  if (p == 0)    corn[0] = v;
  if (p == 31)   corn[1] = v;
  if (p == 992)  corn[2] = v;
  if (p == 1023) corn[3] = v;

  t = wred(t); r0 = wred(r0); r31 = wred(r31); c0 = wred(c0); c31 = wred(c31);
  int warp = p >> 5, lane = p & 31;
  if (lane == 0) { red[warp][0]=t; red[warp][1]=r0; red[warp][2]=r31; red[warp][3]=c0; red[warp][4]=c31; }
  __syncthreads();
  if (p < 32) {
    float a0 = red[p][0], a1 = red[p][1], a2 = red[p][2], a3 = red[p][3], a4 = red[p][4];
    a0 = wred(a0); a1 = wred(a1); a2 = wred(a2); a3 = wred(a3); a4 = wred(a4);
    if (p == 0) {
      float T = a0, R0 = a1, R31 = a2, C0 = a3, C31 = a4;
      float* Sp = g_S + (b * 64 + c) * 9;
      Sp[0] = T - R31 - C31 + corn[3];
      Sp[1] = T - R31;
      Sp[2] = T - R31 - C0 + corn[2];
      Sp[3] = T - C31;
      Sp[4] = T;
      Sp[5] = T - C0;
      Sp[6] = T - R0 - C31 + corn[1];
      Sp[7] = T - R0;
      Sp[8] = T - R0 - C0 + corn[0];
    }
  }
}

// ---------------- K2: qkv 1x1 conv -> Q (scaled by dkh^-0.5 * log2e), K, V ----------------
__global__ void __launch_bounds__(256) qkv_kernel(const float* __restrict__ w,
                                                  const float* __restrict__ bias) {
  int tid = threadIdx.x;        // 256
  int b = blockIdx.z;
  int o0 = blockIdx.y * 8;      // 15 groups of 8 output channels
  __shared__ float ws[512];
  __shared__ float bs[8];
  for (int i = tid; i < 512; i += 256) ws[i] = w[o0 * 64 + i];
  if (tid < 8) bs[tid] = bias[o0 + tid];
  __syncthreads();
  int n0 = tid * 4;
  float4 acc[8];
  #pragma unroll
  for (int u = 0; u < 8; u++) { float bv = bs[u]; acc[u] = make_float4(bv, bv, bv, bv); }
  const float* hp = g_pre + b * 64 * 1024 + n0;
  #pragma unroll 4
  for (int i = 0; i < 64; i++) {
    float4 hv = *(const float4*)(hp + i * 1024);
    #pragma unroll
    for (int u = 0; u < 8; u++) {
      float wv = ws[u * 64 + i];
      acc[u].x = fmaf(wv, hv.x, acc[u].x);
      acc[u].y = fmaf(wv, hv.y, acc[u].y);
      acc[u].z = fmaf(wv, hv.z, acc[u].z);
      acc[u].w = fmaf(wv, hv.w, acc[u].w);
    }
  }
  // Q gets dkh^-0.5 * log2(e) folded in (exp -> ex2 domain; exact, all logit terms linear in q)
  const float QMUL = 0.31622776601683794f * 1.4426950408889634f;
  #pragma unroll
  for (int u = 0; u < 8; u++) {
    int o = o0 + u;
    int which = o / 40;
    int r = o - which * 40;
    int head = r / 10, d = r - head * 10;
    float* dst = (which == 0) ? g_Q : ((which == 1) ? g_Kb : g_Vb);
    float mul = (which == 0) ? QMUL : 1.f;
    float* pb = dst + ((b * 4 + head) * 1024) * 10 + d;
    pb[(n0 + 0) * 10] = acc[u].x * mul;
    pb[(n0 + 1) * 10] = acc[u].y * mul;
    pb[(n0 + 2) * 10] = acc[u].z * mul;
    pb[(n0 + 3) * 10] = acc[u].w * mul;
  }
}

// ---------------- K3: attention (f32x2 packed), 8 query rows / block ----------------
#define ATTN_SMEM ((12288 + 12288 + 640) * 4)

__global__ void __launch_bounds__(256, 2) attn_kernel(const float* __restrict__ krh,
                                                      const float* __restrict__ krw) {
  extern __shared__ float sm[];
  float* Ks = sm;             // [m][12] padded
  float* Vs = sm + 12288;     // [m][12] padded
  float* Hs = sm + 24576;     // key_rel_h 63*10
  int b = blockIdx.z, h = blockIdx.y;
  int bh = b * 4 + h;
  int tid = threadIdx.x;
  int warp = tid >> 5, lane = tid & 31;
  const float* Kp = g_Kb + bh * 10240;
  const float* Vp = g_Vb + bh * 10240;
  for (int i = tid; i < 12288; i += 256) {
    int m = i / 12, d = i - m * 12;
    float kv = 0.f, vv = 0.f;
    if (d < 10) { kv = Kp[m * 10 + d]; vv = Vp[m * 10 + d]; }
    Ks[i] = kv; Vs[i] = vv;
  }
  for (int i = tid; i < 630; i += 256) Hs[i] = krh[i];

  int yq = blockIdx.x * 8 + warp;   // warp = one query row
  int xq = lane;
  int n = yq * 32 + xq;
  const float* qp = g_Q + (bh * 1024 + n) * 10;   // pre-scaled by dkh^-.5*log2e; 40B rows (8B aligned)
  u64 Q01 = ldf2(qp), Q23 = ldf2(qp + 2), Q45 = ldf2(qp + 4),
      Q67 = ldf2(qp + 6), Q89 = ldf2(qp + 8);

  // rw[xm] = q . key_rel_w[xm - xq + 31]   (already in log2e domain)
  float rw[32];
  #pragma unroll
  for (int xm = 0; xm < 32; xm++) {
    const float* kr = krw + (xm - xq + 31) * 10;
    u64 s2 = fmul2(Q01, ldf2(kr));
    s2 = ffma2(Q23, ldf2(kr + 2), s2);
    s2 = ffma2(Q45, ldf2(kr + 4), s2);
    s2 = ffma2(Q67, ldf2(kr + 6), s2);
    s2 = ffma2(Q89, ldf2(kr + 8), s2);
    float2 sp = unpack2(s2);
    rw[xm] = sp.x + sp.y;
  }
  __syncthreads();

  u64 a01 = 0ull, a23 = 0ull, a45 = 0ull, a67 = 0ull, a89 = 0ull;
  float l = 0.f;
  #pragma unroll 1
  for (int ym = 0; ym < 32; ym++) {
    const float* kh = Hs + (ym - yq + 31) * 10;   // smem broadcast (yq const per warp)
    u64 r2 = fmul2(Q01, ldf2(kh));
    r2 = ffma2(Q23, ldf2(kh + 2), r2);
    r2 = ffma2(Q45, ldf2(kh + 4), r2);
    r2 = ffma2(Q67, ldf2(kh + 6), r2);
    r2 = ffma2(Q89, ldf2(kh + 8), r2);
    float2 rr = unpack2(r2);
    float rh = rr.x + rr.y;
    const float* kr = Ks + ym * 384;
    const float* vr = Vs + ym * 384;
    #pragma unroll
    for (int xm = 0; xm < 32; xm++) {
      F4U ka; ka.f4 = *(const float4*)(kr + xm * 12);
      F4U kb; kb.f4 = *(const float4*)(kr + xm * 12 + 4);
      F2U kc; kc.f2 = *(const float2*)(kr + xm * 12 + 8);
      u64 s2 = ffma2(Q01, ka.u2.x, pack2(rh, rw[xm]));
      s2 = ffma2(Q23, ka.u2.y, s2);
      s2 = ffma2(Q45, kb.u2.x, s2);
      s2 = ffma2(Q67, kb.u2.y, s2);
      s2 = ffma2(Q89, kc.u, s2);
      float2 sp = unpack2(s2);
      float p = ex2f(sp.x + sp.y);     // logits tiny; no max-subtract needed
      l += p;
      u64 p2 = pack2(p, p);
      F4U va; va.f4 = *(const float4*)(vr + xm * 12);
      F4U vb; vb.f4 = *(const float4*)(vr + xm * 12 + 4);
      F2U vc; vc.f2 = *(const float2*)(vr + xm * 12 + 8);
      a01 = ffma2(p2, va.u2.x, a01);
      a23 = ffma2(p2, va.u2.y, a23);
      a45 = ffma2(p2, vb.u2.x, a45);
      a67 = ffma2(p2, vb.u2.y, a67);
      a89 = ffma2(p2, vc.u, a89);
    }
  }
  float inv = __frcp_rn(l);
  u64 inv2 = pack2(inv, inv);
  u64* op = (u64*)(g_attn + (bh * 1024 + n) * 10);
  op[0] = fmul2(a01, inv2);
  op[1] = fmul2(a23, inv2);
  op[2] = fmul2(a45, inv2);
  op[3] = fmul2(a67, inv2);
  op[4] = fmul2(a89, inv2);
}

// ---------------- K4: poolconv + attn pooling + attno + fc ----------------
__global__ void final_kernel(const float* __restrict__ convo_w,
                             const float* __restrict__ convo_b,
                             const float* __restrict__ attno_w,
                             const float* __restrict__ attno_b,
                             const float* __restrict__ fc_w,
                             const float* __restrict__ fc_b,
                             float* __restrict__ out) {
  int b = blockIdx.x, tid = threadIdx.x;  // 256 threads
  int warp = tid >> 5, lane = tid & 31;
  __shared__ float Ssm[576];
  __shared__ float pooled[88];
  __shared__ float mean_s[40], pa[40];
  for (int i = tid; i < 576; i += 256) Ssm[i] = g_S[b * 576 + i];
  __syncthreads();

  // pooled conv_out: 88 channels, warp per channel (8 warps x 11)
  #pragma unroll
  for (int i = 0; i < 11; i++) {
    int oc = warp * 11 + i;
    float acc = 0.f;
    const float* wp = convo_w + oc * 576;
    #pragma unroll
    for (int j = lane; j < 576; j += 32) acc = fmaf(__ldg(&wp[j]), Ssm[j], acc);
    acc = wred(acc);
    if (lane == 0) pooled[oc] = __ldg(&convo_b[oc]) + acc * (1.f / 1024.f);
  }

  // attn channel means: channel c = mean of 1024 consecutive floats of (n,d)-flat attn
  #pragma unroll
  for (int cc = 0; cc < 5; cc++) {
    int c = warp * 5 + cc;
    const float* p = g_attn + b * 40960 + c * 1024;
    float s = 0.f;
    #pragma unroll 4
    for (int j = lane; j < 1024; j += 32) s += p[j];
    s = wred(s);
    if (lane == 0) mean_s[c] = s * (1.f / 1024.f);
  }
  __syncthreads();
  if (tid < 40) {
    float acc = __ldg(&attno_b[tid]);
    #pragma unroll 4
    for (int c = 0; c < 40; c++) acc = fmaf(__ldg(&attno_w[tid * 40 + c]), mean_s[c], acc);
    pa[tid] = acc;
  }
  __syncthreads();
  if (tid < 100) {
    float acc = __ldg(&fc_b[tid]);
    const float* wp = fc_w + tid * 128;
    #pragma unroll 4
    for (int c = 0; c < 88; c++) acc = fmaf(__ldg(&wp[c]), pooled[c], acc);
    #pragma unroll 4
    for (int c = 0; c < 40; c++) acc = fmaf(__ldg(&wp[88 + c]), pa[c], acc);
    out[b * 100 + tid] = acc;
  }
}

// ---------------- launch ----------------
extern "C" void kernel_launch(void* const* d_in, const int* in_sizes, int n_in,
                              void* d_out, int out_size) {
  const float* x         = (const float*)d_in[0];
  const float* conv1_w   = (const float*)d_in[1];
  const float* conv1_b   = (const float*)d_in[2];
  const float* bn1_g     = (const float*)d_in[3];
  const float* bn1_b     = (const float*)d_in[4];
  const float* convo_w   = (const float*)d_in[5];
  const float* convo_b   = (const float*)d_in[6];
  const float* qkv_w     = (const float*)d_in[7];
  const float* qkv_b     = (const float*)d_in[8];
  const float* attno_w   = (const float*)d_in[9];
  const float* attno_b   = (const float*)d_in[10];
  const float* key_rel_h = (const float*)d_in[11];
  const float* key_rel_w = (const float*)d_in[12];
  const float* fc_w      = (const float*)d_in[13];
  const float* fc_b      = (const float*)d_in[14];
  float* out = (float*)d_out;

  cudaFuncSetAttribute(attn_kernel, cudaFuncAttributeMaxDynamicSharedMemorySize, ATTN_SMEM);

  conv1_kernel<<<dim3(64, 16), 256>>>(x, conv1_w, conv1_b);     // our #0
  bnrelu_kernel<<<dim3(64, 16), 1024>>>(bn1_g, bn1_b);          // our #1
  qkv_kernel<<<dim3(1, 15, 16), 256>>>(qkv_w, qkv_b);           // our #2
  attn_kernel<<<dim3(4, 4, 16), 256, ATTN_SMEM>>>(key_rel_h, key_rel_w);  // our #3 (profiled)
  final_kernel<<<16, 256>>>(convo_w, convo_b, attno_w, attno_b, fc_w, fc_b, out);
}

// round 5
// speedup vs baseline: 2.1879x; 1.1817x over previous
#include <cuda_runtime.h>

typedef unsigned long long u64;

// ---------------- scratch (device globals; no allocation) ----------------
__device__ float g_pre[16*64*1024];     // conv1 out, then h (in-place)
__device__ float2 g_bstats[64*16];      // per (oc,b) partial {sum, sumsq}
__device__ float g_S[16*64*9];          // 9 shifted window sums per (b, in-ch)
__device__ float g_Q[16*4*1024*10];
__device__ float g_KV[16*4*1024*20];    // interleaved K(10) | V(10) per key
__device__ float g_attn[16*4*1024*10];

__device__ __forceinline__ float wred(float v) {
  #pragma unroll
  for (int o = 16; o; o >>= 1) v += __shfl_down_sync(0xffffffffu, v, o);
  return v;
}

// ---- packed f32x2 helpers (sm_100+) ----
__device__ __forceinline__ u64 ffma2(u64 a, u64 b, u64 c) {
  u64 d; asm("fma.rn.f32x2 %0, %1, %2, %3;" : "=l"(d) : "l"(a), "l"(b), "l"(c)); return d;
}
__device__ __forceinline__ u64 fmul2(u64 a, u64 b) {
  u64 d; asm("mul.rn.f32x2 %0, %1, %2;" : "=l"(d) : "l"(a), "l"(b)); return d;
}
__device__ __forceinline__ u64 pack2(float lo, float hi) {
  u64 r; asm("mov.b64 %0, {%1, %2};" : "=l"(r) : "f"(lo), "f"(hi)); return r;
}
__device__ __forceinline__ float2 unpack2(u64 v) {
  float lo, hi; asm("mov.b64 {%0, %1}, %2;" : "=f"(lo), "=f"(hi) : "l"(v));
  return make_float2(lo, hi);
}
__device__ __forceinline__ float ex2f(float x) {
  float y; asm("ex2.approx.f32 %0, %1;" : "=f"(y) : "f"(x)); return y;
}

union F4U { float4 f4; ulonglong2 u2; };
union F2U { float2 f2; u64 u; };

__device__ __forceinline__ u64 ldf2(const float* p) {
  F2U t; t.f2 = *(const float2*)p; return t.u;
}

// ---------------- K0: conv1 3x3 (3->64) SAME + per-block BN partial stats ----------------
__global__ void __launch_bounds__(256) conv1_kernel(const float* __restrict__ x,
                                                    const float* __restrict__ w,
                                                    const float* __restrict__ bias) {
  int t = threadIdx.x;
  int oc = blockIdx.x, b = blockIdx.y;
  int p0 = t * 4;
  int y = p0 >> 5, x0 = p0 & 31;
  float w_[27];
  #pragma unroll
  for (int i = 0; i < 27; i++) w_[i] = __ldg(&w[oc * 27 + i]);
  float bv = __ldg(&bias[oc]);
  float a0 = bv, a1 = bv, a2 = bv, a3 = bv;
  #pragma unroll
  for (int ic = 0; ic < 3; ic++) {
    const float* base = x + (b * 3 + ic) * 1024;
    #pragma unroll
    for (int ky = 0; ky < 3; ky++) {
      int iy = y + ky - 1;
      if (iy < 0 || iy > 31) continue;
      const float* row = base + iy * 32;
      float r[6];
      #pragma unroll
      for (int dx = 0; dx < 6; dx++) {
        int c = x0 - 1 + dx;
        r[dx] = (c >= 0 && c < 32) ? __ldg(&row[c]) : 0.f;
      }
      #pragma unroll
      for (int kx = 0; kx < 3; kx++) {
        float wv = w_[ic * 9 + ky * 3 + kx];
        a0 = fmaf(wv, r[kx],     a0);
        a1 = fmaf(wv, r[kx + 1], a1);
        a2 = fmaf(wv, r[kx + 2], a2);
        a3 = fmaf(wv, r[kx + 3], a3);
      }
    }
  }
  *(float4*)(g_pre + (b * 64 + oc) * 1024 + p0) = make_float4(a0, a1, a2, a3);

  float s  = a0 + a1 + a2 + a3;
  float sq = fmaf(a0, a0, fmaf(a1, a1, fmaf(a2, a2, a3 * a3)));
  s = wred(s); sq = wred(sq);
  __shared__ float ss[8], s2m[8];
  int warp = t >> 5, lane = t & 31;
  if (lane == 0) { ss[warp] = s; s2m[warp] = sq; }
  __syncthreads();
  if (t == 0) {
    float S = 0.f, Q = 0.f;
    #pragma unroll
    for (int i = 0; i < 8; i++) { S += ss[i]; Q += s2m[i]; }
    g_bstats[oc * 16 + b] = make_float2(S, Q);
  }
}

// ---------------- K1: BN finalize + apply + relu (in place) + 9 window sums ----------------
__global__ void bnrelu_kernel(const float* __restrict__ gamma,
                              const float* __restrict__ beta) {
  int c = blockIdx.x, b = blockIdx.y;
  int p = threadIdx.x;                  // 1024 threads
  __shared__ float scb[2];
  if (p < 16) {
    float2 v = g_bstats[c * 16 + p];
    float s = v.x, q = v.y;
    #pragma unroll
    for (int o = 8; o; o >>= 1) {
      s += __shfl_down_sync(0xffffu, s, o, 16);
      q += __shfl_down_sync(0xffffu, q, o, 16);
    }
    if (p == 0) {
      float mean = s * (1.f / 16384.f);
      float var  = q * (1.f / 16384.f) - mean * mean;
      float sc = __ldg(&gamma[c]) * rsqrtf(var + 1e-5f);
      scb[0] = sc;
      scb[1] = __ldg(&beta[c]) - mean * sc;
    }
  }
  __syncthreads();

  int y = p >> 5, xx = p & 31;
  int idx = (b * 64 + c) * 1024 + p;
  float v = fmaxf(fmaf(g_pre[idx], scb[0], scb[1]), 0.f);
  g_pre[idx] = v;

  float t = v;
  float r0  = (y == 0)  ? v : 0.f;
  float r31 = (y == 31) ? v : 0.f;
  float c0  = (xx == 0)  ? v : 0.f;
  float c31 = (xx == 31) ? v : 0.f;

  __shared__ float red[32][5];
  __shared__ float corn[4];
  if (p == 0)    corn[0] = v;
  if (p == 31)   corn[1] = v;
  if (p == 992)  corn[2] = v;
  if (p == 1023) corn[3] = v;

  t = wred(t); r0 = wred(r0); r31 = wred(r31); c0 = wred(c0); c31 = wred(c31);
  int warp = p >> 5, lane = p & 31;
  if (lane == 0) { red[warp][0]=t; red[warp][1]=r0; red[warp][2]=r31; red[warp][3]=c0; red[warp][4]=c31; }
  __syncthreads();
  if (p < 32) {
    float a0 = red[p][0], a1 = red[p][1], a2 = red[p][2], a3 = red[p][3], a4 = red[p][4];
    a0 = wred(a0); a1 = wred(a1); a2 = wred(a2); a3 = wred(a3); a4 = wred(a4);
    if (p == 0) {
      float T = a0, R0 = a1, R31 = a2, C0 = a3, C31 = a4;
      float* Sp = g_S + (b * 64 + c) * 9;
      Sp[0] = T - R31 - C31 + corn[3];
      Sp[1] = T - R31;
      Sp[2] = T - R31 - C0 + corn[2];
      Sp[3] = T - C31;
      Sp[4] = T;
      Sp[5] = T - C0;
      Sp[6] = T - R0 - C31 + corn[1];
      Sp[7] = T - R0;
      Sp[8] = T - R0 - C0 + corn[0];
    }
  }
}

// ---------------- K2: qkv 1x1 conv -> Q (scaled), KV interleaved ----------------
__global__ void __launch_bounds__(256) qkv_kernel(const float* __restrict__ w,
                                                  const float* __restrict__ bias) {
  int tid = threadIdx.x;        // 256
  int b = blockIdx.z;
  int o0 = blockIdx.y * 8;      // 15 groups of 8 output channels
  __shared__ float ws[512];
  __shared__ float bs[8];
  for (int i = tid; i < 512; i += 256) ws[i] = w[o0 * 64 + i];
  if (tid < 8) bs[tid] = bias[o0 + tid];
  __syncthreads();
  int n0 = tid * 4;
  float4 acc[8];
  #pragma unroll
  for (int u = 0; u < 8; u++) { float bv = bs[u]; acc[u] = make_float4(bv, bv, bv, bv); }
  const float* hp = g_pre + b * 64 * 1024 + n0;
  #pragma unroll 4
  for (int i = 0; i < 64; i++) {
    float4 hv = *(const float4*)(hp + i * 1024);
    #pragma unroll
    for (int u = 0; u < 8; u++) {
      float wv = ws[u * 64 + i];
      acc[u].x = fmaf(wv, hv.x, acc[u].x);
      acc[u].y = fmaf(wv, hv.y, acc[u].y);
      acc[u].z = fmaf(wv, hv.z, acc[u].z);
      acc[u].w = fmaf(wv, hv.w, acc[u].w);
    }
  }
  // Q gets dkh^-0.5 * log2(e) folded in (exp -> ex2 domain; exact)
  const float QMUL = 0.31622776601683794f * 1.4426950408889634f;
  #pragma unroll
  for (int u = 0; u < 8; u++) {
    int o = o0 + u;
    int which = o / 40;
    int r = o - which * 40;
    int head = r / 10, d = r - head * 10;
    int bh = b * 4 + head;
    if (which == 0) {
      float* pb = g_Q + (bh * 1024) * 10 + d;
      pb[(n0 + 0) * 10] = acc[u].x * QMUL;
      pb[(n0 + 1) * 10] = acc[u].y * QMUL;
      pb[(n0 + 2) * 10] = acc[u].z * QMUL;
      pb[(n0 + 3) * 10] = acc[u].w * QMUL;
    } else {
      float* pb = g_KV + (bh * 1024) * 20 + ((which == 1) ? d : 10 + d);
      pb[(n0 + 0) * 20] = acc[u].x;
      pb[(n0 + 1) * 20] = acc[u].y;
      pb[(n0 + 2) * 20] = acc[u].z;
      pb[(n0 + 3) * 20] = acc[u].w;
    }
  }
}

// ---------------- K3: attention, 2 queries/thread, KV interleaved ----------------
// smem: KV 1024*20 floats (81920B) + krh 630 (2520B) + krw 630 (2520B)
#define ATTN_SMEM ((20480 + 640 + 640) * 4)

__global__ void __launch_bounds__(128) attn_kernel(const float* __restrict__ krh,
                                                   const float* __restrict__ krw) {
  extern __shared__ float sm[];
  float* KVs = sm;               // [m][20]
  float* Hs  = sm + 20480;       // key_rel_h 63*10
  float* Ws  = sm + 21120;       // key_rel_w 63*10
  int b = blockIdx.z, h = blockIdx.y;
  int bh = b * 4 + h;
  int tid = threadIdx.x;         // 128
  int warp = tid >> 5, lane = tid & 31;

  // stage KV (coalesced float4 copy) + rel tables
  {
    const float4* src = (const float4*)(g_KV + bh * 20480);
    float4* dst = (float4*)KVs;
    #pragma unroll 8
    for (int i = tid; i < 5120; i += 128) dst[i] = src[i];
    for (int i = tid; i < 630; i += 128) { Hs[i] = krh[i]; Ws[i] = krw[i]; }
  }

  int ya = blockIdx.x * 8 + warp;        // query row A
  int yb = ya + 4;                       // query row B
  int xq = lane;
  int na = ya * 32 + xq, nb = yb * 32 + xq;
  const float* qa = g_Q + (bh * 1024 + na) * 10;
  const float* qb = g_Q + (bh * 1024 + nb) * 10;
  u64 Qa01 = ldf2(qa), Qa23 = ldf2(qa + 2), Qa45 = ldf2(qa + 4),
      Qa67 = ldf2(qa + 6), Qa89 = ldf2(qa + 8);
  u64 Qb01 = ldf2(qb), Qb23 = ldf2(qb + 2), Qb45 = ldf2(qb + 4),
      Qb67 = ldf2(qb + 6), Qb89 = ldf2(qb + 8);

  __syncthreads();

  // rw[xm] per query (same xq -> shared krw rows)
  float rwa[32], rwb[32];
  #pragma unroll
  for (int xm = 0; xm < 32; xm++) {
    const float* kr = Ws + (xm - xq + 31) * 10;
    u64 k01 = ldf2(kr), k23 = ldf2(kr + 2), k45 = ldf2(kr + 4),
        k67 = ldf2(kr + 6), k89 = ldf2(kr + 8);
    u64 sa = fmul2(Qa01, k01);
    sa = ffma2(Qa23, k23, sa); sa = ffma2(Qa45, k45, sa);
    sa = ffma2(Qa67, k67, sa); sa = ffma2(Qa89, k89, sa);
    u64 sb = fmul2(Qb01, k01);
    sb = ffma2(Qb23, k23, sb); sb = ffma2(Qb45, k45, sb);
    sb = ffma2(Qb67, k67, sb); sb = ffma2(Qb89, k89, sb);
    float2 fa = unpack2(sa), fb = unpack2(sb);
    rwa[xm] = fa.x + fa.y;
    rwb[xm] = fb.x + fb.y;
  }

  u64 Aa01 = 0, Aa23 = 0, Aa45 = 0, Aa67 = 0, Aa89 = 0;
  u64 Ab01 = 0, Ab23 = 0, Ab45 = 0, Ab67 = 0, Ab89 = 0;
  float la = 0.f, lb = 0.f;
  #pragma unroll 1
  for (int ym = 0; ym < 32; ym++) {
    const float* kha = Hs + (ym - ya + 31) * 10;
    const float* khb = Hs + (ym - yb + 31) * 10;
    u64 ra = fmul2(Qa01, ldf2(kha));
    ra = ffma2(Qa23, ldf2(kha + 2), ra); ra = ffma2(Qa45, ldf2(kha + 4), ra);
    ra = ffma2(Qa67, ldf2(kha + 6), ra); ra = ffma2(Qa89, ldf2(kha + 8), ra);
    u64 rb = fmul2(Qb01, ldf2(khb));
    rb = ffma2(Qb23, ldf2(khb + 2), rb); rb = ffma2(Qb45, ldf2(khb + 4), rb);
    rb = ffma2(Qb67, ldf2(khb + 6), rb); rb = ffma2(Qb89, ldf2(khb + 8), rb);
    float2 fra = unpack2(ra), frb = unpack2(rb);
    float rha = fra.x + fra.y, rhb = frb.x + frb.y;

    const float4* kv = (const float4*)(KVs + ym * 640);
    #pragma unroll
    for (int xm = 0; xm < 32; xm++) {
      F4U c0, c1, c2, c3, c4;
      c0.f4 = kv[xm * 5];      // K0..K3
      c1.f4 = kv[xm * 5 + 1];  // K4..K7
      c2.f4 = kv[xm * 5 + 2];  // K8,K9,V0,V1
      c3.f4 = kv[xm * 5 + 3];  // V2..V5
      c4.f4 = kv[xm * 5 + 4];  // V6..V9
      u64 sa = ffma2(Qa01, c0.u2.x, pack2(rha, rwa[xm]));
      sa = ffma2(Qa23, c0.u2.y, sa);
      sa = ffma2(Qa45, c1.u2.x, sa);
      sa = ffma2(Qa67, c1.u2.y, sa);
      sa = ffma2(Qa89, c2.u2.x, sa);
      u64 sb = ffma2(Qb01, c0.u2.x, pack2(rhb, rwb[xm]));
      sb = ffma2(Qb23, c0.u2.y, sb);
      sb = ffma2(Qb45, c1.u2.x, sb);
      sb = ffma2(Qb67, c1.u2.y, sb);
      sb = ffma2(Qb89, c2.u2.x, sb);
      float2 pa2 = unpack2(sa), pb2 = unpack2(sb);
      float pa = ex2f(pa2.x + pa2.y);
      float pb = ex2f(pb2.x + pb2.y);
      la += pa; lb += pb;
      u64 Pa = pack2(pa, pa), Pb = pack2(pb, pb);
      Aa01 = ffma2(Pa, c2.u2.y, Aa01);
      Aa23 = ffma2(Pa, c3.u2.x, Aa23);
      Aa45 = ffma2(Pa, c3.u2.y, Aa45);
      Aa67 = ffma2(Pa, c4.u2.x, Aa67);
      Aa89 = ffma2(Pa, c4.u2.y, Aa89);
      Ab01 = ffma2(Pb, c2.u2.y, Ab01);
      Ab23 = ffma2(Pb, c3.u2.x, Ab23);
      Ab45 = ffma2(Pb, c3.u2.y, Ab45);
      Ab67 = ffma2(Pb, c4.u2.x, Ab67);
      Ab89 = ffma2(Pb, c4.u2.y, Ab89);
    }
  }
  float inva = __frcp_rn(la), invb = __frcp_rn(lb);
  u64 ia = pack2(inva, inva), ib = pack2(invb, invb);
  u64* oa = (u64*)(g_attn + (bh * 1024 + na) * 10);
  oa[0] = fmul2(Aa01, ia); oa[1] = fmul2(Aa23, ia); oa[2] = fmul2(Aa45, ia);
  oa[3] = fmul2(Aa67, ia); oa[4] = fmul2(Aa89, ia);
  u64* ob = (u64*)(g_attn + (bh * 1024 + nb) * 10);
  ob[0] = fmul2(Ab01, ib); ob[1] = fmul2(Ab23, ib); ob[2] = fmul2(Ab45, ib);
  ob[3] = fmul2(Ab67, ib); ob[4] = fmul2(Ab89, ib);
}

// ---------------- K4: poolconv + attn pooling + attno + fc ----------------
__global__ void final_kernel(const float* __restrict__ convo_w,
                             const float* __restrict__ convo_b,
                             const float* __restrict__ attno_w,
                             const float* __restrict__ attno_b,
                             const float* __restrict__ fc_w,
                             const float* __restrict__ fc_b,
                             float* __restrict__ out) {
  int b = blockIdx.x, tid = threadIdx.x;  // 256 threads
  int warp = tid >> 5, lane = tid & 31;
  __shared__ float Ssm[576];
  __shared__ float pooled[88];
  __shared__ float mean_s[40], pa[40];
  for (int i = tid; i < 576; i += 256) Ssm[i] = g_S[b * 576 + i];
  __syncthreads();

  #pragma unroll
  for (int i = 0; i < 11; i++) {
    int oc = warp * 11 + i;
    float acc = 0.f;
    const float* wp = convo_w + oc * 576;
    #pragma unroll
    for (int j = lane; j < 576; j += 32) acc = fmaf(__ldg(&wp[j]), Ssm[j], acc);
    acc = wred(acc);
    if (lane == 0) pooled[oc] = __ldg(&convo_b[oc]) + acc * (1.f / 1024.f);
  }

  #pragma unroll
  for (int cc = 0; cc < 5; cc++) {
    int c = warp * 5 + cc;
    const float* p = g_attn + b * 40960 + c * 1024;
    float s = 0.f;
    #pragma unroll 4
    for (int j = lane; j < 1024; j += 32) s += p[j];
    s = wred(s);
    if (lane == 0) mean_s[c] = s * (1.f / 1024.f);
  }
  __syncthreads();
  if (tid < 40) {
    float acc = __ldg(&attno_b[tid]);
    #pragma unroll 4
    for (int c = 0; c < 40; c++) acc = fmaf(__ldg(&attno_w[tid * 40 + c]), mean_s[c], acc);
    pa[tid] = acc;
  }
  __syncthreads();
  if (tid < 100) {
    float acc = __ldg(&fc_b[tid]);
    const float* wp = fc_w + tid * 128;
    #pragma unroll 4
    for (int c = 0; c < 88; c++) acc = fmaf(__ldg(&wp[c]), pooled[c], acc);
    #pragma unroll 4
    for (int c = 0; c < 40; c++) acc = fmaf(__ldg(&wp[88 + c]), pa[c], acc);
    out[b * 100 + tid] = acc;
  }
}

// ---------------- launch ----------------
extern "C" void kernel_launch(void* const* d_in, const int* in_sizes, int n_in,
                              void* d_out, int out_size) {
  const float* x         = (const float*)d_in[0];
  const float* conv1_w   = (const float*)d_in[1];
  const float* conv1_b   = (const float*)d_in[2];
  const float* bn1_g     = (const float*)d_in[3];
  const float* bn1_b     = (const float*)d_in[4];
  const float* convo_w   = (const float*)d_in[5];
  const float* convo_b   = (const float*)d_in[6];
  const float* qkv_w     = (const float*)d_in[7];
  const float* qkv_b     = (const float*)d_in[8];
  const float* attno_w   = (const float*)d_in[9];
  const float* attno_b   = (const float*)d_in[10];
  const float* key_rel_h = (const float*)d_in[11];
  const float* key_rel_w = (const float*)d_in[12];
  const float* fc_w      = (const float*)d_in[13];
  const float* fc_b      = (const float*)d_in[14];
  float* out = (float*)d_out;

  cudaFuncSetAttribute(attn_kernel, cudaFuncAttributeMaxDynamicSharedMemorySize, ATTN_SMEM);

  conv1_kernel<<<dim3(64, 16), 256>>>(x, conv1_w, conv1_b);     // #0
  bnrelu_kernel<<<dim3(64, 16), 1024>>>(bn1_g, bn1_b);          // #1
  qkv_kernel<<<dim3(1, 15, 16), 256>>>(qkv_w, qkv_b);           // #2
  attn_kernel<<<dim3(4, 4, 16), 128, ATTN_SMEM>>>(key_rel_h, key_rel_w);  // #3 (profiled)
  final_kernel<<<16, 256>>>(convo_w, convo_b, attno_w, attno_b, fc_w, fc_b, out);
}